// round 15
// baseline (speedup 1.0000x reference)
#include <cuda_runtime.h>
#include <cuda_bf16.h>
#include <cuda_fp16.h>
#include <stdint.h>
#include <cstdint>
#include <math.h>

#define Bv 4
#define Sv 2048
#define Hv 16
#define Dv 64
#define DM 1024
#define Mv (Bv*Sv)   // 8192

// ---------------------------------------------------------------------------
// Scratch
// ---------------------------------------------------------------------------
__device__ float g_cos[Sv*32];
__device__ float g_sin[Sv*32];

__device__ __half g_xh [Mv*DM];
__device__ __half g_yh [Mv*DM];
__device__ __half g_wh [4*DM*DM];
__device__ __half g_qh [Mv*DM];
__device__ __half g_kh [Mv*DM];
__device__ __half g_vh [Mv*DM];

// ---------------------------------------------------------------------------
// prep kernels
// ---------------------------------------------------------------------------
__global__ void tohalf_kernel(const float* __restrict__ s,
                              __half* __restrict__ o, int n)
{
    int i = blockIdx.x * blockDim.x + threadIdx.x;
    if (i >= n) return;
    o[i] = __float2half_rn(s[i]);
}

__global__ void conv4_half_kernel(const float* __restrict__ s0, const float* __restrict__ s1,
                                  const float* __restrict__ s2, const float* __restrict__ s3,
                                  __half* __restrict__ o, int n)
{
    int i = blockIdx.x * blockDim.x + threadIdx.x;
    if (i >= 4 * n) return;
    int w = i / n, r = i - w * n;
    const float* src = (w == 0) ? s0 : (w == 1) ? s1 : (w == 2) ? s2 : s3;
    o[i] = __float2half_rn(src[r]);
}

__global__ void rope_table_kernel() {
    int idx = blockIdx.x * blockDim.x + threadIdx.x;
    if (idx >= Sv * 32) return;
    int pos = idx >> 5;
    int i   = idx & 31;
    double inv = pow(10000.0, -(double)i / 32.0);
    double ang = (double)pos * inv;
    g_cos[idx] = (float)cos(ang);
    g_sin[idx] = (float)sin(ang);
}

// ---------------------------------------------------------------------------
// primitives
// ---------------------------------------------------------------------------
__device__ __forceinline__ void ldmx4(unsigned& r0, unsigned& r1,
                                      unsigned& r2, unsigned& r3, unsigned a) {
    asm volatile("ldmatrix.sync.aligned.m8n8.x4.shared.b16 {%0,%1,%2,%3}, [%4];"
        : "=r"(r0), "=r"(r1), "=r"(r2), "=r"(r3) : "r"(a));
}
__device__ __forceinline__ void ldmx4t(unsigned& r0, unsigned& r1,
                                       unsigned& r2, unsigned& r3, unsigned a) {
    asm volatile("ldmatrix.sync.aligned.m8n8.x4.trans.shared.b16 {%0,%1,%2,%3}, [%4];"
        : "=r"(r0), "=r"(r1), "=r"(r2), "=r"(r3) : "r"(a));
}
__device__ __forceinline__ void mma16816h(float* c, const unsigned* a, const unsigned* b) {
    asm volatile(
        "mma.sync.aligned.m16n8k16.row.col.f32.f16.f16.f32 "
        "{%0,%1,%2,%3}, {%4,%5,%6,%7}, {%8,%9}, {%0,%1,%2,%3};"
        : "+f"(c[0]), "+f"(c[1]), "+f"(c[2]), "+f"(c[3])
        : "r"(a[0]), "r"(a[1]), "r"(a[2]), "r"(a[3]), "r"(b[0]), "r"(b[1]));
}
__device__ __forceinline__ void cpa16(void* smem, const void* g) {
    unsigned s = (unsigned)__cvta_generic_to_shared(smem);
    asm volatile("cp.async.cg.shared.global [%0], [%1], 16;" :: "r"(s), "l"(g));
}
__device__ __forceinline__ void cp_commit() { asm volatile("cp.async.commit_group;"); }
template<int N> __device__ __forceinline__ void cp_wait() {
    asm volatile("cp.async.wait_group %0;" :: "n"(N));
}
__device__ __forceinline__ float ex2f(float x) {
    float y;
    asm("ex2.approx.ftz.f32 %0, %1;" : "=f"(y) : "f"(x));
    return y;
}

#define APAD 40
#define BPAD2 136
#define AS_OFF(s, r, c)  ((s) * 5120 + (r) * APAD + (c))
#define BS_OFF(s, r, c)  (15360 + (s) * 4352 + (r) * BPAD2 + (c))
#define G256_SMEM ((15360 + 3 * 4352) * sizeof(__half))   // 56832 B

// ---------------------------------------------------------------------------
// 256-thread GEMM: BM=128 BN=128 BK=32, 1-term fp16 weights, 3-stage cp.async,
// ONE sync per k-tile, rotating counters, pointer increments.
// MODE 0: fp32 out (Cf + bias)   MODE 1: rope*scl -> fp16   MODE 2: fp16
// ---------------------------------------------------------------------------
template<int MODE>
__global__ __launch_bounds__(256, 3) void gemm256(
    const __half* __restrict__ Ah, const __half* __restrict__ Bw,
    const float* __restrict__ bias,
    __half* __restrict__ C1, float* __restrict__ Cf,
    int bnoff, float scl)
{
    extern __shared__ __half sm[];

    int tid = threadIdx.x, lane = tid & 31, warp = tid >> 5;
    int wm = warp >> 2, wn = warp & 3;
    int bn = (blockIdx.x << 7) + bnoff;
    int bm = blockIdx.y << 7;

    float acc[4][4][4];
#pragma unroll
    for (int i = 0; i < 4; i++)
#pragma unroll
        for (int j = 0; j < 4; j++)
#pragma unroll
            for (int e = 0; e < 4; e++) acc[i][j][e] = 0.f;

    int u0k = tid >> 4, u0n = (tid & 15) << 3;
    int arow = tid >> 1;
    int ac0 = (tid & 1) << 4;
    const __half* Ap0 = Ah + (size_t)(bm + arow) * DM;

    // prologue: k-tiles 0,1 into stages 0,1
#pragma unroll
    for (int pk = 0; pk < 2; pk++) {
        int k0 = pk << 5;
        cpa16(&sm[AS_OFF(pk, arow, ac0)],     Ap0 + k0 + ac0);
        cpa16(&sm[AS_OFF(pk, arow, ac0 + 8)], Ap0 + k0 + ac0 + 8);
        cpa16(&sm[BS_OFF(pk, u0k, u0n)],      Bw + (size_t)(k0 + u0k) * DM + bn + u0n);
        cpa16(&sm[BS_OFF(pk, u0k + 16, u0n)], Bw + (size_t)(k0 + u0k + 16) * DM + bn + u0n);
        cp_commit();
    }

    const __half* ApPre  = Ap0 + 64 + ac0;
    const __half* BpPre0 = Bw + (size_t)(64 + u0k) * DM + bn + u0n;
    const __half* BpPre1 = BpPre0 + (size_t)16 * DM;

    const int NKT = DM >> 5;   // 32
    int scur = 0, sfill = 2;
    for (int kt = 0; kt < NKT; kt++) {
        if (kt + 1 < NKT) { cp_wait<1>(); } else { cp_wait<0>(); }
        __syncthreads();
        if (kt + 2 < NKT) {
            cpa16(&sm[AS_OFF(sfill, arow, ac0)],     ApPre);
            cpa16(&sm[AS_OFF(sfill, arow, ac0 + 8)], ApPre + 8);
            cpa16(&sm[BS_OFF(sfill, u0k, u0n)],      BpPre0);
            cpa16(&sm[BS_OFF(sfill, u0k + 16, u0n)], BpPre1);
            cp_commit();
            ApPre  += 32;
            BpPre0 += (size_t)32 * DM;
            BpPre1 += (size_t)32 * DM;
            sfill = (sfill == 2) ? 0 : sfill + 1;
        }

#pragma unroll
        for (int ks = 0; ks < 2; ks++) {
            int k16 = ks << 4;
            unsigned Af[4][4];
            int ar = (lane & 15);
            int ac = k16 + ((lane >> 4) << 3);
#pragma unroll
            for (int mt = 0; mt < 4; mt++) {
                int m0 = wm * 64 + mt * 16;
                unsigned a0 = (unsigned)__cvta_generic_to_shared(
                    &sm[AS_OFF(scur, m0 + ar, ac)]);
                ldmx4(Af[mt][0], Af[mt][1], Af[mt][2], Af[mt][3], a0);
            }
            unsigned Bf[4][2];
            int bkr = k16 + (lane & 7) + (lane & 8);
#pragma unroll
            for (int p = 0; p < 2; p++) {
                int n0 = wn * 32 + p * 16 + (((lane >> 4) & 1) << 3);
                unsigned r0, r1, r2, r3;
                unsigned ad = (unsigned)__cvta_generic_to_shared(
                    &sm[BS_OFF(scur, bkr, n0)]);
                ldmx4t(r0, r1, r2, r3, ad);
                Bf[p * 2][0] = r0; Bf[p * 2][1] = r1;
                Bf[p * 2 + 1][0] = r2; Bf[p * 2 + 1][1] = r3;
            }
#pragma unroll
            for (int mt = 0; mt < 4; mt++)
#pragma unroll
                for (int nt = 0; nt < 4; nt++)
                    mma16816h(acc[mt][nt], Af[mt], Bf[nt]);
        }
        scur = (scur == 2) ? 0 : scur + 1;
    }

    // ---- epilogue ----
    int gid = lane >> 2, tq = lane & 3;
#pragma unroll
    for (int mt = 0; mt < 4; mt++) {
        int row = bm + wm * 64 + mt * 16 + gid;
#pragma unroll
        for (int nt = 0; nt < 4; nt++) {
            int col = bn + wn * 32 + nt * 8 + tq * 2;
            float b0 = bias[col], b1 = bias[col + 1];
            float v0 = acc[mt][nt][0] + b0;
            float v1 = acc[mt][nt][1] + b1;
            float v2 = acc[mt][nt][2] + b0;
            float v3 = acc[mt][nt][3] + b1;
            if (MODE == 0) {
                *(float2*)&Cf[(size_t)row * DM + col] = make_float2(v0, v1);
                *(float2*)&Cf[(size_t)(row + 8) * DM + col] = make_float2(v2, v3);
            } else if (MODE == 2) {
                *(__half2*)&C1[(size_t)row * DM + col] = __floats2half2_rn(v0, v1);
                *(__half2*)&C1[(size_t)(row + 8) * DM + col] = __floats2half2_rn(v2, v3);
            } else {
                int i = (col >> 1) & 31;
                int s1 = row & (Sv - 1);
                float c1 = g_cos[(s1 << 5) + i],       sn1 = g_sin[(s1 << 5) + i];
                float c2 = g_cos[((s1 + 8) << 5) + i], sn2 = g_sin[((s1 + 8) << 5) + i];
                float r0 = (v0 * c1 - v1 * sn1) * scl;
                float r1 = (v1 * c1 + v0 * sn1) * scl;
                float r2 = (v2 * c2 - v3 * sn2) * scl;
                float r3 = (v3 * c2 + v2 * sn2) * scl;
                *(__half2*)&C1[(size_t)row * DM + col] = __floats2half2_rn(r0, r1);
                *(__half2*)&C1[(size_t)(row + 8) * DM + col] = __floats2half2_rn(r2, r3);
            }
        }
    }
}

// ---------------------------------------------------------------------------
// Flash attention: 256 threads, Q tile 128, KV tile 64, all fp16 single-term,
// cp.async double-buffered, no-rescale exp2 softmax. (unchanged from R13)
// ---------------------------------------------------------------------------
#define KPAD 72
#define BUF_ELEMS (64*KPAD)
#define STG_ELEMS (2*BUF_ELEMS)
#define FLASH_SMEM (2*STG_ELEMS*sizeof(__half))  // 36864

__global__ __launch_bounds__(256) void flash_mma(
    const __half* __restrict__ qh, const __half* __restrict__ kh,
    const __half* __restrict__ vh,
    __half* __restrict__ yh)
{
    extern __shared__ __half smx[];

    int tid = threadIdx.x, lane = tid & 31, warp = tid >> 5;
    int qt = (int)gridDim.x - 1 - (int)blockIdx.x;
    int h = blockIdx.y, b = blockIdx.z;
    int qg0 = qt * 128;
    size_t base = ((size_t)b * Sv) * DM + h * Dv;
    int gid = lane >> 2, tig = lane & 3;

    const __half* srcs[2] = {kh, vh};

#pragma unroll
    for (int p = 0; p < 4; p++) {
        int idx = p * 256 + tid;
        int row = idx >> 3, c = idx & 7;
        cpa16(&smx[STG_ELEMS + row * KPAD + c * 8],
              qh + base + (size_t)(qg0 + row) * DM + c * 8);
    }
    cp_commit();
#pragma unroll
    for (int p = 0; p < 4; p++) {
        int buf = p >> 1;
        int idx = ((p & 1) << 8) + tid;
        int row = idx >> 3, c = idx & 7;
        cpa16(&smx[buf * BUF_ELEMS + row * KPAD + c * 8],
              srcs[buf] + base + (size_t)row * DM + c * 8);
    }
    cp_commit();

    cp_wait<1>();
    __syncthreads();

    unsigned Qf[4][4];
    {
        int r = warp * 16 + (lane & 15);
        int c = (lane >> 4) << 3;
#pragma unroll
        for (int kt = 0; kt < 4; kt++) {
            unsigned a = (unsigned)__cvta_generic_to_shared(
                &smx[STG_ELEMS + r * KPAD + kt * 16 + c]);
            ldmx4(Qf[kt][0], Qf[kt][1], Qf[kt][2], Qf[kt][3], a);
        }
    }
    __syncthreads();

    int krow = (lane & 7) + ((lane >> 4) << 3);
    int kcol = ((lane >> 3) & 1) << 3;
    int vrow = (lane & 7) + (((lane >> 3) & 1) << 3);
    int vcol = (lane >> 4) << 3;

    float acc_o[8][4];
#pragma unroll
    for (int i = 0; i < 8; i++)
#pragma unroll
        for (int e = 0; e < 4; e++) acc_o[i][e] = 0.f;
    float lsum0 = 0.f, lsum1 = 0.f;
    int row0g = qg0 + warp * 16 + gid;

    int n = 2 * qt + 2;
    for (int j = 0; j < n; j++) {
        int s = j & 1;
        if (j + 1 < n) {
            int sb = (1 - s) * STG_ELEMS;
            size_t grow = base + (size_t)(j + 1) * 64 * DM;
#pragma unroll
            for (int p = 0; p < 4; p++) {
                int buf = p >> 1;
                int idx = ((p & 1) << 8) + tid;
                int row = idx >> 3, c = idx & 7;
                cpa16(&smx[sb + buf * BUF_ELEMS + row * KPAD + c * 8],
                      srcs[buf] + grow + (size_t)row * DM + c * 8);
            }
            cp_commit();
            cp_wait<1>();
        } else {
            cp_wait<0>();
        }
        __syncthreads();

        __half* Kh_ = smx + s * STG_ELEMS;
        __half* Vh_ = Kh_ + BUF_ELEMS;

        float sc[8][4];
#pragma unroll
        for (int i = 0; i < 8; i++)
#pragma unroll
            for (int e = 0; e < 4; e++) sc[i][e] = 0.f;

#pragma unroll
        for (int kt = 0; kt < 4; kt++) {
            unsigned Kf[8][2];
#pragma unroll
            for (int ng = 0; ng < 4; ng++) {
                unsigned r0, r1, r2, r3;
                unsigned a = (unsigned)__cvta_generic_to_shared(
                    &Kh_[(ng * 16 + krow) * KPAD + kt * 16 + kcol]);
                ldmx4(r0, r1, r2, r3, a);
                Kf[ng * 2][0] = r0; Kf[ng * 2][1] = r1;
                Kf[ng * 2 + 1][0] = r2; Kf[ng * 2 + 1][1] = r3;
            }
#pragma unroll
            for (int nt = 0; nt < 8; nt++)
                mma16816h(sc[nt], Qf[kt], Kf[nt]);
        }

        if (j >= 2 * qt) {
#pragma unroll
            for (int nt = 0; nt < 8; nt++) {
#pragma unroll
                for (int e = 0; e < 4; e++) {
                    int col = j * 64 + nt * 8 + 2 * tig + (e & 1);
                    int row = row0g + ((e >> 1) << 3);
                    sc[nt][e] = (col > row) ? 0.f : ex2f(sc[nt][e]);
                }
                lsum0 += sc[nt][0] + sc[nt][1];
                lsum1 += sc[nt][2] + sc[nt][3];
            }
        } else {
#pragma unroll
            for (int nt = 0; nt < 8; nt++) {
                sc[nt][0] = ex2f(sc[nt][0]);
                sc[nt][1] = ex2f(sc[nt][1]);
                sc[nt][2] = ex2f(sc[nt][2]);
                sc[nt][3] = ex2f(sc[nt][3]);
                lsum0 += sc[nt][0] + sc[nt][1];
                lsum1 += sc[nt][2] + sc[nt][3];
            }
        }

#pragma unroll
        for (int kt = 0; kt < 4; kt++) {
            unsigned Ph[4];
#pragma unroll
            for (int half = 0; half < 2; half++) {
                int nt = 2 * kt + half;
                __half2 h0 = __floats2half2_rn(sc[nt][0], sc[nt][1]);
                __half2 h1 = __floats2half2_rn(sc[nt][2], sc[nt][3]);
                Ph[half * 2]     = *(unsigned*)&h0;
                Ph[half * 2 + 1] = *(unsigned*)&h1;
            }
            unsigned Vf[8][2];
#pragma unroll
            for (int dg = 0; dg < 4; dg++) {
                unsigned r0, r1, r2, r3;
                unsigned a = (unsigned)__cvta_generic_to_shared(
                    &Vh_[(kt * 16 + vrow) * KPAD + dg * 16 + vcol]);
                ldmx4t(r0, r1, r2, r3, a);
                Vf[dg * 2][0] = r0; Vf[dg * 2][1] = r1;
                Vf[dg * 2 + 1][0] = r2; Vf[dg * 2 + 1][1] = r3;
            }
#pragma unroll
            for (int dnt = 0; dnt < 8; dnt++)
                mma16816h(acc_o[dnt], Ph, Vf[dnt]);
        }
        __syncthreads();
    }

    lsum0 += __shfl_xor_sync(0xffffffffu, lsum0, 1);
    lsum0 += __shfl_xor_sync(0xffffffffu, lsum0, 2);
    lsum1 += __shfl_xor_sync(0xffffffffu, lsum1, 1);
    lsum1 += __shfl_xor_sync(0xffffffffu, lsum1, 2);
    float inv0 = 1.f / lsum0, inv1 = 1.f / lsum1;
    size_t o0 = ((size_t)b * Sv + row0g) * DM + h * Dv;
    size_t o1 = o0 + (size_t)8 * DM;
#pragma unroll
    for (int dnt = 0; dnt < 8; dnt++) {
        int col = dnt * 8 + 2 * tig;
        *(__half2*)&yh[o0 + col] =
            __floats2half2_rn(acc_o[dnt][0] * inv0, acc_o[dnt][1] * inv0);
        *(__half2*)&yh[o1 + col] =
            __floats2half2_rn(acc_o[dnt][2] * inv1, acc_o[dnt][3] * inv1);
    }
}

// ---------------------------------------------------------------------------
// kernel_launch
// ---------------------------------------------------------------------------
extern "C" void kernel_launch(void* const* d_in, const int* in_sizes, int n_in,
                              void* d_out, int out_size)
{
    const float* x  = (const float*)d_in[0];
    const float* Wq = (const float*)d_in[1];
    const float* bq = (const float*)d_in[2];
    const float* Wk = (const float*)d_in[3];
    const float* bk = (const float*)d_in[4];
    const float* Wv = (const float*)d_in[5];
    const float* bv = (const float*)d_in[6];
    const float* Wo = (const float*)d_in[7];
    const float* bo = (const float*)d_in[8];
    float* out = (float*)d_out;

    __half *xh, *yh, *wh, *qh, *kh, *vh;
    cudaGetSymbolAddress((void**)&xh, g_xh);
    cudaGetSymbolAddress((void**)&yh, g_yh);
    cudaGetSymbolAddress((void**)&wh, g_wh);
    cudaGetSymbolAddress((void**)&qh, g_qh);
    cudaGetSymbolAddress((void**)&kh, g_kh);
    cudaGetSymbolAddress((void**)&vh, g_vh);

    cudaFuncSetAttribute(gemm256<0>,
                         cudaFuncAttributeMaxDynamicSharedMemorySize, (int)G256_SMEM);
    cudaFuncSetAttribute(gemm256<1>,
                         cudaFuncAttributeMaxDynamicSharedMemorySize, (int)G256_SMEM);
    cudaFuncSetAttribute(gemm256<2>,
                         cudaFuncAttributeMaxDynamicSharedMemorySize, (int)G256_SMEM);
    cudaFuncSetAttribute(flash_mma,
                         cudaFuncAttributeMaxDynamicSharedMemorySize, (int)FLASH_SMEM);

    const int NX = Mv * DM;
    const int NW = DM * DM;
    const float QSCL = 0.125f * 1.4426950408889634f;   // exp2 softmax

    rope_table_kernel<<<(Sv * 32 + 255) / 256, 256>>>();
    conv4_half_kernel<<<(4 * NW + 255) / 256, 256>>>(Wq, Wk, Wv, Wo, wh, NW);
    tohalf_kernel<<<(NX + 255) / 256, 256>>>(x, xh, NX);

    // QKV projections (one template per output flavor; Q/K rope-fused)
    dim3 gg(DM / 128, Mv / 128);
    gemm256<1><<<gg, 256, G256_SMEM>>>(xh, wh + 0 * (size_t)NW, bq, qh, nullptr, 0, QSCL);
    gemm256<1><<<gg, 256, G256_SMEM>>>(xh, wh + 1 * (size_t)NW, bk, kh, nullptr, 0, 1.0f);
    gemm256<2><<<gg, 256, G256_SMEM>>>(xh, wh + 2 * (size_t)NW, bv, vh, nullptr, 0, 1.0f);

    // attention
    dim3 att_grid(Sv / 128, Hv, Bv);
    flash_mma<<<att_grid, 256, FLASH_SMEM>>>(qh, kh, vh, yh);

    // out = y@Wo + bo -> fp32
    gemm256<0><<<gg, 256, G256_SMEM>>>(yh, wh + 3 * (size_t)NW, bo, nullptr, out, 0, 1.0f);
}

// round 16
// speedup vs baseline: 1.5311x; 1.5311x over previous
#include <cuda_runtime.h>
#include <cuda_bf16.h>
#include <cuda_fp16.h>
#include <stdint.h>
#include <cstdint>
#include <math.h>

#define Bv 4
#define Sv 2048
#define Hv 16
#define Dv 64
#define DM 1024
#define Mv (Bv*Sv)   // 8192

// ---------------------------------------------------------------------------
// Scratch
// ---------------------------------------------------------------------------
__device__ float g_cos[Sv*32];
__device__ float g_sin[Sv*32];

__device__ __half g_xh [Mv*DM];
__device__ __half g_yh [Mv*DM];
__device__ __half g_wh [4*DM*DM];
__device__ __half g_qh [Mv*DM];
__device__ __half g_kh [Mv*DM];
__device__ __half g_vh [Mv*DM];

// ---------------------------------------------------------------------------
// prep kernels
// ---------------------------------------------------------------------------
__global__ void tohalf_kernel(const float* __restrict__ s,
                              __half* __restrict__ o, int n)
{
    int i = blockIdx.x * blockDim.x + threadIdx.x;
    if (i >= n) return;
    o[i] = __float2half_rn(s[i]);
}

__global__ void conv4_half_kernel(const float* __restrict__ s0, const float* __restrict__ s1,
                                  const float* __restrict__ s2, const float* __restrict__ s3,
                                  __half* __restrict__ o, int n)
{
    int i = blockIdx.x * blockDim.x + threadIdx.x;
    if (i >= 4 * n) return;
    int w = i / n, r = i - w * n;
    const float* src = (w == 0) ? s0 : (w == 1) ? s1 : (w == 2) ? s2 : s3;
    o[i] = __float2half_rn(src[r]);
}

__global__ void rope_table_kernel() {
    int idx = blockIdx.x * blockDim.x + threadIdx.x;
    if (idx >= Sv * 32) return;
    int pos = idx >> 5;
    int i   = idx & 31;
    double inv = pow(10000.0, -(double)i / 32.0);
    double ang = (double)pos * inv;
    g_cos[idx] = (float)cos(ang);
    g_sin[idx] = (float)sin(ang);
}

// ---------------------------------------------------------------------------
// primitives
// ---------------------------------------------------------------------------
__device__ __forceinline__ void ldmx4(unsigned& r0, unsigned& r1,
                                      unsigned& r2, unsigned& r3, unsigned a) {
    asm volatile("ldmatrix.sync.aligned.m8n8.x4.shared.b16 {%0,%1,%2,%3}, [%4];"
        : "=r"(r0), "=r"(r1), "=r"(r2), "=r"(r3) : "r"(a));
}
__device__ __forceinline__ void ldmx4t(unsigned& r0, unsigned& r1,
                                       unsigned& r2, unsigned& r3, unsigned a) {
    asm volatile("ldmatrix.sync.aligned.m8n8.x4.trans.shared.b16 {%0,%1,%2,%3}, [%4];"
        : "=r"(r0), "=r"(r1), "=r"(r2), "=r"(r3) : "r"(a));
}
__device__ __forceinline__ void mma16816h(float* c, const unsigned* a, const unsigned* b) {
    asm volatile(
        "mma.sync.aligned.m16n8k16.row.col.f32.f16.f16.f32 "
        "{%0,%1,%2,%3}, {%4,%5,%6,%7}, {%8,%9}, {%0,%1,%2,%3};"
        : "+f"(c[0]), "+f"(c[1]), "+f"(c[2]), "+f"(c[3])
        : "r"(a[0]), "r"(a[1]), "r"(a[2]), "r"(a[3]), "r"(b[0]), "r"(b[1]));
}
__device__ __forceinline__ void cpa16(void* smem, const void* g) {
    unsigned s = (unsigned)__cvta_generic_to_shared(smem);
    asm volatile("cp.async.cg.shared.global [%0], [%1], 16;" :: "r"(s), "l"(g));
}
__device__ __forceinline__ void cp_commit() { asm volatile("cp.async.commit_group;"); }
template<int N> __device__ __forceinline__ void cp_wait() {
    asm volatile("cp.async.wait_group %0;" :: "n"(N));
}
__device__ __forceinline__ float ex2f(float x) {
    float y;
    asm("ex2.approx.ftz.f32 %0, %1;" : "=f"(y) : "f"(x));
    return y;
}

#define APAD 40
#define BPAD2 136
#define AS_OFF(s, r, c)  ((s) * 5120 + (r) * APAD + (c))
#define BS_OFF(s, r, c)  (15360 + (s) * 4352 + (r) * BPAD2 + (c))
#define G256_SMEM ((15360 + 3 * 4352) * sizeof(__half))   // 56832 B

// ---------------------------------------------------------------------------
// Shared 256-thread GEMM body (macro-free inline function, no lambdas):
// BM=128 BN=128 BK=32, 1-term fp16 weights, 3-stage cp.async, 1 sync/kt,
// rotating counters, pre-incremented pointers. Result left in acc[][][].
// ---------------------------------------------------------------------------
__device__ __forceinline__ void gemm256_core(
    const __half* __restrict__ Ah, const __half* __restrict__ Bw,
    int bm, int bn, float acc[4][4][4])
{
    extern __shared__ __half sm[];
    int tid = threadIdx.x, lane = tid & 31;

#pragma unroll
    for (int i = 0; i < 4; i++)
#pragma unroll
        for (int j = 0; j < 4; j++)
#pragma unroll
            for (int e = 0; e < 4; e++) acc[i][j][e] = 0.f;

    int u0k = tid >> 4, u0n = (tid & 15) << 3;
    int arow = tid >> 1;
    int ac0 = (tid & 1) << 4;
    const __half* Ap0 = Ah + (size_t)(bm + arow) * DM;

#pragma unroll
    for (int pk = 0; pk < 2; pk++) {
        int k0 = pk << 5;
        cpa16(&sm[AS_OFF(pk, arow, ac0)],     Ap0 + k0 + ac0);
        cpa16(&sm[AS_OFF(pk, arow, ac0 + 8)], Ap0 + k0 + ac0 + 8);
        cpa16(&sm[BS_OFF(pk, u0k, u0n)],      Bw + (size_t)(k0 + u0k) * DM + bn + u0n);
        cpa16(&sm[BS_OFF(pk, u0k + 16, u0n)], Bw + (size_t)(k0 + u0k + 16) * DM + bn + u0n);
        cp_commit();
    }

    const __half* ApPre  = Ap0 + 64 + ac0;
    const __half* BpPre0 = Bw + (size_t)(64 + u0k) * DM + bn + u0n;
    const __half* BpPre1 = BpPre0 + (size_t)16 * DM;

    int wm = (tid >> 5) >> 2, wn = (tid >> 5) & 3;
    const int NKT = DM >> 5;   // 32
    int scur = 0, sfill = 2;
    for (int kt = 0; kt < NKT; kt++) {
        if (kt + 1 < NKT) { cp_wait<1>(); } else { cp_wait<0>(); }
        __syncthreads();
        if (kt + 2 < NKT) {
            cpa16(&sm[AS_OFF(sfill, arow, ac0)],     ApPre);
            cpa16(&sm[AS_OFF(sfill, arow, ac0 + 8)], ApPre + 8);
            cpa16(&sm[BS_OFF(sfill, u0k, u0n)],      BpPre0);
            cpa16(&sm[BS_OFF(sfill, u0k + 16, u0n)], BpPre1);
            cp_commit();
            ApPre  += 32;
            BpPre0 += (size_t)32 * DM;
            BpPre1 += (size_t)32 * DM;
            sfill = (sfill == 2) ? 0 : sfill + 1;
        }

#pragma unroll
        for (int ks = 0; ks < 2; ks++) {
            int k16 = ks << 4;
            unsigned Af[4][4];
            int ar = (lane & 15);
            int ac = k16 + ((lane >> 4) << 3);
#pragma unroll
            for (int mt = 0; mt < 4; mt++) {
                int m0 = wm * 64 + mt * 16;
                unsigned a0 = (unsigned)__cvta_generic_to_shared(
                    &sm[AS_OFF(scur, m0 + ar, ac)]);
                ldmx4(Af[mt][0], Af[mt][1], Af[mt][2], Af[mt][3], a0);
            }
            unsigned Bf[4][2];
            int bkr = k16 + (lane & 7) + (lane & 8);
#pragma unroll
            for (int p = 0; p < 2; p++) {
                int n0 = wn * 32 + p * 16 + (((lane >> 4) & 1) << 3);
                unsigned r0, r1, r2, r3;
                unsigned ad = (unsigned)__cvta_generic_to_shared(
                    &sm[BS_OFF(scur, bkr, n0)]);
                ldmx4t(r0, r1, r2, r3, ad);
                Bf[p * 2][0] = r0; Bf[p * 2][1] = r1;
                Bf[p * 2 + 1][0] = r2; Bf[p * 2 + 1][1] = r3;
            }
#pragma unroll
            for (int mt = 0; mt < 4; mt++)
#pragma unroll
                for (int nt = 0; nt < 4; nt++)
                    mma16816h(acc[mt][nt], Af[mt], Bf[nt]);
        }
        scur = (scur == 2) ? 0 : scur + 1;
    }
}

// ---------------------------------------------------------------------------
// Fused QKV GEMM (grid.x = 24: [0,8)=Q [8,16)=K [16,24)=V), NO min-CTA bound.
// ---------------------------------------------------------------------------
__global__ __launch_bounds__(256) void gemm_qkv(
    const __half* __restrict__ xh, const __half* __restrict__ wh,
    const float* __restrict__ bq, const float* __restrict__ bk,
    const float* __restrict__ bv,
    __half* __restrict__ qout, __half* __restrict__ kout,
    __half* __restrict__ vout, float qscl)
{
    int bx = blockIdx.x;
    int w = bx >> 3;
    int bn = (bx & 7) << 7;
    int bm = blockIdx.y << 7;
    const __half* Bw = wh + (size_t)w * DM * DM;
    const float* bias = (w == 0) ? bq : (w == 1) ? bk : bv;
    __half* Cout = (w == 0) ? qout : (w == 1) ? kout : vout;
    float scl = (w == 0) ? qscl : 1.0f;
    bool dorope = (w < 2);

    float acc[4][4][4];
    gemm256_core(xh, Bw, bm, bn, acc);

    int tid = threadIdx.x, lane = tid & 31, warp = tid >> 5;
    int wm = warp >> 2, wn = warp & 3;
    int gid = lane >> 2, tq = lane & 3;
#pragma unroll
    for (int mt = 0; mt < 4; mt++) {
        int row = bm + wm * 64 + mt * 16 + gid;
#pragma unroll
        for (int nt = 0; nt < 4; nt++) {
            int col = bn + wn * 32 + nt * 8 + tq * 2;
            float b0 = bias[col], b1 = bias[col + 1];
            float v0 = acc[mt][nt][0] + b0;
            float v1 = acc[mt][nt][1] + b1;
            float v2 = acc[mt][nt][2] + b0;
            float v3 = acc[mt][nt][3] + b1;
            if (!dorope) {
                *(__half2*)&Cout[(size_t)row * DM + col] = __floats2half2_rn(v0, v1);
                *(__half2*)&Cout[(size_t)(row + 8) * DM + col] = __floats2half2_rn(v2, v3);
            } else {
                int i = (col >> 1) & 31;
                int s1 = row & (Sv - 1);
                float c1 = g_cos[(s1 << 5) + i],       sn1 = g_sin[(s1 << 5) + i];
                float c2 = g_cos[((s1 + 8) << 5) + i], sn2 = g_sin[((s1 + 8) << 5) + i];
                float r0 = (v0 * c1 - v1 * sn1) * scl;
                float r1 = (v1 * c1 + v0 * sn1) * scl;
                float r2 = (v2 * c2 - v3 * sn2) * scl;
                float r3 = (v3 * c2 + v2 * sn2) * scl;
                *(__half2*)&Cout[(size_t)row * DM + col] = __floats2half2_rn(r0, r1);
                *(__half2*)&Cout[(size_t)(row + 8) * DM + col] = __floats2half2_rn(r2, r3);
            }
        }
    }
}

// ---------------------------------------------------------------------------
// O-projection GEMM: same 256-thread BN=128 body, fp32 out, NO min-CTA bound.
// ---------------------------------------------------------------------------
__global__ __launch_bounds__(256) void gemm_o(
    const __half* __restrict__ yh, const __half* __restrict__ Bw,
    const float* __restrict__ bias, float* __restrict__ out)
{
    int bn = blockIdx.x << 7;
    int bm = blockIdx.y << 7;

    float acc[4][4][4];
    gemm256_core(yh, Bw, bm, bn, acc);

    int tid = threadIdx.x, lane = tid & 31, warp = tid >> 5;
    int wm = warp >> 2, wn = warp & 3;
    int gid = lane >> 2, tq = lane & 3;
#pragma unroll
    for (int mt = 0; mt < 4; mt++) {
        int row = bm + wm * 64 + mt * 16 + gid;
#pragma unroll
        for (int nt = 0; nt < 4; nt++) {
            int col = bn + wn * 32 + nt * 8 + tq * 2;
            float b0 = bias[col], b1 = bias[col + 1];
            *(float2*)&out[(size_t)row * DM + col] =
                make_float2(acc[mt][nt][0] + b0, acc[mt][nt][1] + b1);
            *(float2*)&out[(size_t)(row + 8) * DM + col] =
                make_float2(acc[mt][nt][2] + b0, acc[mt][nt][3] + b1);
        }
    }
}

// ---------------------------------------------------------------------------
// Flash attention: 256 threads, Q tile 128, KV tile 64, all fp16 single-term,
// cp.async double-buffered, no-rescale exp2 softmax. (unchanged from R13)
// ---------------------------------------------------------------------------
#define KPAD 72
#define BUF_ELEMS (64*KPAD)
#define STG_ELEMS (2*BUF_ELEMS)
#define FLASH_SMEM (2*STG_ELEMS*sizeof(__half))  // 36864

__global__ __launch_bounds__(256) void flash_mma(
    const __half* __restrict__ qh, const __half* __restrict__ kh,
    const __half* __restrict__ vh,
    __half* __restrict__ yh)
{
    extern __shared__ __half smx[];

    int tid = threadIdx.x, lane = tid & 31, warp = tid >> 5;
    int qt = (int)gridDim.x - 1 - (int)blockIdx.x;
    int h = blockIdx.y, b = blockIdx.z;
    int qg0 = qt * 128;
    size_t base = ((size_t)b * Sv) * DM + h * Dv;
    int gid = lane >> 2, tig = lane & 3;

    const __half* srcs[2] = {kh, vh};

#pragma unroll
    for (int p = 0; p < 4; p++) {
        int idx = p * 256 + tid;
        int row = idx >> 3, c = idx & 7;
        cpa16(&smx[STG_ELEMS + row * KPAD + c * 8],
              qh + base + (size_t)(qg0 + row) * DM + c * 8);
    }
    cp_commit();
#pragma unroll
    for (int p = 0; p < 4; p++) {
        int buf = p >> 1;
        int idx = ((p & 1) << 8) + tid;
        int row = idx >> 3, c = idx & 7;
        cpa16(&smx[buf * BUF_ELEMS + row * KPAD + c * 8],
              srcs[buf] + base + (size_t)row * DM + c * 8);
    }
    cp_commit();

    cp_wait<1>();
    __syncthreads();

    unsigned Qf[4][4];
    {
        int r = warp * 16 + (lane & 15);
        int c = (lane >> 4) << 3;
#pragma unroll
        for (int kt = 0; kt < 4; kt++) {
            unsigned a = (unsigned)__cvta_generic_to_shared(
                &smx[STG_ELEMS + r * KPAD + kt * 16 + c]);
            ldmx4(Qf[kt][0], Qf[kt][1], Qf[kt][2], Qf[kt][3], a);
        }
    }
    __syncthreads();

    int krow = (lane & 7) + ((lane >> 4) << 3);
    int kcol = ((lane >> 3) & 1) << 3;
    int vrow = (lane & 7) + (((lane >> 3) & 1) << 3);
    int vcol = (lane >> 4) << 3;

    float acc_o[8][4];
#pragma unroll
    for (int i = 0; i < 8; i++)
#pragma unroll
        for (int e = 0; e < 4; e++) acc_o[i][e] = 0.f;
    float lsum0 = 0.f, lsum1 = 0.f;
    int row0g = qg0 + warp * 16 + gid;

    int n = 2 * qt + 2;
    for (int j = 0; j < n; j++) {
        int s = j & 1;
        if (j + 1 < n) {
            int sb = (1 - s) * STG_ELEMS;
            size_t grow = base + (size_t)(j + 1) * 64 * DM;
#pragma unroll
            for (int p = 0; p < 4; p++) {
                int buf = p >> 1;
                int idx = ((p & 1) << 8) + tid;
                int row = idx >> 3, c = idx & 7;
                cpa16(&smx[sb + buf * BUF_ELEMS + row * KPAD + c * 8],
                      srcs[buf] + grow + (size_t)row * DM + c * 8);
            }
            cp_commit();
            cp_wait<1>();
        } else {
            cp_wait<0>();
        }
        __syncthreads();

        __half* Kh_ = smx + s * STG_ELEMS;
        __half* Vh_ = Kh_ + BUF_ELEMS;

        float sc[8][4];
#pragma unroll
        for (int i = 0; i < 8; i++)
#pragma unroll
            for (int e = 0; e < 4; e++) sc[i][e] = 0.f;

#pragma unroll
        for (int kt = 0; kt < 4; kt++) {
            unsigned Kf[8][2];
#pragma unroll
            for (int ng = 0; ng < 4; ng++) {
                unsigned r0, r1, r2, r3;
                unsigned a = (unsigned)__cvta_generic_to_shared(
                    &Kh_[(ng * 16 + krow) * KPAD + kt * 16 + kcol]);
                ldmx4(r0, r1, r2, r3, a);
                Kf[ng * 2][0] = r0; Kf[ng * 2][1] = r1;
                Kf[ng * 2 + 1][0] = r2; Kf[ng * 2 + 1][1] = r3;
            }
#pragma unroll
            for (int nt = 0; nt < 8; nt++)
                mma16816h(sc[nt], Qf[kt], Kf[nt]);
        }

        if (j >= 2 * qt) {
#pragma unroll
            for (int nt = 0; nt < 8; nt++) {
#pragma unroll
                for (int e = 0; e < 4; e++) {
                    int col = j * 64 + nt * 8 + 2 * tig + (e & 1);
                    int row = row0g + ((e >> 1) << 3);
                    sc[nt][e] = (col > row) ? 0.f : ex2f(sc[nt][e]);
                }
                lsum0 += sc[nt][0] + sc[nt][1];
                lsum1 += sc[nt][2] + sc[nt][3];
            }
        } else {
#pragma unroll
            for (int nt = 0; nt < 8; nt++) {
                sc[nt][0] = ex2f(sc[nt][0]);
                sc[nt][1] = ex2f(sc[nt][1]);
                sc[nt][2] = ex2f(sc[nt][2]);
                sc[nt][3] = ex2f(sc[nt][3]);
                lsum0 += sc[nt][0] + sc[nt][1];
                lsum1 += sc[nt][2] + sc[nt][3];
            }
        }

#pragma unroll
        for (int kt = 0; kt < 4; kt++) {
            unsigned Ph[4];
#pragma unroll
            for (int half = 0; half < 2; half++) {
                int nt = 2 * kt + half;
                __half2 h0 = __floats2half2_rn(sc[nt][0], sc[nt][1]);
                __half2 h1 = __floats2half2_rn(sc[nt][2], sc[nt][3]);
                Ph[half * 2]     = *(unsigned*)&h0;
                Ph[half * 2 + 1] = *(unsigned*)&h1;
            }
            unsigned Vf[8][2];
#pragma unroll
            for (int dg = 0; dg < 4; dg++) {
                unsigned r0, r1, r2, r3;
                unsigned a = (unsigned)__cvta_generic_to_shared(
                    &Vh_[(kt * 16 + vrow) * KPAD + dg * 16 + vcol]);
                ldmx4t(r0, r1, r2, r3, a);
                Vf[dg * 2][0] = r0; Vf[dg * 2][1] = r1;
                Vf[dg * 2 + 1][0] = r2; Vf[dg * 2 + 1][1] = r3;
            }
#pragma unroll
            for (int dnt = 0; dnt < 8; dnt++)
                mma16816h(acc_o[dnt], Ph, Vf[dnt]);
        }
        __syncthreads();
    }

    lsum0 += __shfl_xor_sync(0xffffffffu, lsum0, 1);
    lsum0 += __shfl_xor_sync(0xffffffffu, lsum0, 2);
    lsum1 += __shfl_xor_sync(0xffffffffu, lsum1, 1);
    lsum1 += __shfl_xor_sync(0xffffffffu, lsum1, 2);
    float inv0 = 1.f / lsum0, inv1 = 1.f / lsum1;
    size_t o0 = ((size_t)b * Sv + row0g) * DM + h * Dv;
    size_t o1 = o0 + (size_t)8 * DM;
#pragma unroll
    for (int dnt = 0; dnt < 8; dnt++) {
        int col = dnt * 8 + 2 * tig;
        *(__half2*)&yh[o0 + col] =
            __floats2half2_rn(acc_o[dnt][0] * inv0, acc_o[dnt][1] * inv0);
        *(__half2*)&yh[o1 + col] =
            __floats2half2_rn(acc_o[dnt][2] * inv1, acc_o[dnt][3] * inv1);
    }
}

// ---------------------------------------------------------------------------
// kernel_launch
// ---------------------------------------------------------------------------
extern "C" void kernel_launch(void* const* d_in, const int* in_sizes, int n_in,
                              void* d_out, int out_size)
{
    const float* x  = (const float*)d_in[0];
    const float* Wq = (const float*)d_in[1];
    const float* bq = (const float*)d_in[2];
    const float* Wk = (const float*)d_in[3];
    const float* bk = (const float*)d_in[4];
    const float* Wv = (const float*)d_in[5];
    const float* bv = (const float*)d_in[6];
    const float* Wo = (const float*)d_in[7];
    const float* bo = (const float*)d_in[8];
    float* out = (float*)d_out;

    __half *xh, *yh, *wh, *qh, *kh, *vh;
    cudaGetSymbolAddress((void**)&xh, g_xh);
    cudaGetSymbolAddress((void**)&yh, g_yh);
    cudaGetSymbolAddress((void**)&wh, g_wh);
    cudaGetSymbolAddress((void**)&qh, g_qh);
    cudaGetSymbolAddress((void**)&kh, g_kh);
    cudaGetSymbolAddress((void**)&vh, g_vh);

    cudaFuncSetAttribute(gemm_qkv,
                         cudaFuncAttributeMaxDynamicSharedMemorySize, (int)G256_SMEM);
    cudaFuncSetAttribute(gemm_o,
                         cudaFuncAttributeMaxDynamicSharedMemorySize, (int)G256_SMEM);
    cudaFuncSetAttribute(flash_mma,
                         cudaFuncAttributeMaxDynamicSharedMemorySize, (int)FLASH_SMEM);

    const int NX = Mv * DM;
    const int NW = DM * DM;
    const float QSCL = 0.125f * 1.4426950408889634f;   // exp2 softmax

    rope_table_kernel<<<(Sv * 32 + 255) / 256, 256>>>();
    conv4_half_kernel<<<(4 * NW + 255) / 256, 256>>>(Wq, Wk, Wv, Wo, wh, NW);
    tohalf_kernel<<<(NX + 255) / 256, 256>>>(x, xh, NX);

    // fused QKV projection + rope + fp16 quantization
    dim3 qkv_grid(24, Mv / 128);
    gemm_qkv<<<qkv_grid, 256, G256_SMEM>>>(xh, wh, bq, bk, bv, qh, kh, vh, QSCL);

    // attention
    dim3 att_grid(Sv / 128, Hv, Bv);
    flash_mma<<<att_grid, 256, FLASH_SMEM>>>(qh, kh, vh, yh);

    // out = y@Wo + bo -> fp32
    dim3 og(DM / 128, Mv / 128);
    gemm_o<<<og, 256, G256_SMEM>>>(yh, wh + 3 * (size_t)NW, bo, out);
}